// round 16
// baseline (speedup 1.0000x reference)
#include <cuda_runtime.h>
#include <math.h>

#define BB 2
#define CC 256
#define NN 4096
#define HH 4
#define KK 16
#define DD 64
#define EPSBN 1e-5f
#define SCALE 0.125f

// ---------------- scratch ----------------
__device__ float g_qT  [BB*NN*CC];
__device__ float g_kvT [BB*NN*2*CC];
__device__ float g_ao  [BB*CC*NN];
__device__ float g_x1  [BB*CC*NN];
__device__ float g_hbuf[BB*4*CC*NN];
__device__ int   g_nbr [BB*NN*KK];
__device__ float g_bias[BB*NN*HH*KK];
__device__ float g_w2h [HH*CC];
__device__ float g_u1x [CC], g_u1y[CC], g_u1z[CC];
__device__ float g_rpsh[CC];
__device__ float g_bn1s[CC], g_bn1sh[CC];
__device__ float g_bn2s[CC], g_bn2sh[CC];

// ---------------- helpers ----------------
__device__ __forceinline__ void mma_tf32(float c[4],
                                         const unsigned a[4],
                                         const unsigned b[2]) {
    asm volatile(
        "mma.sync.aligned.m16n8k8.row.col.f32.tf32.tf32.f32 "
        "{%0,%1,%2,%3}, {%4,%5,%6,%7}, {%8,%9}, {%0,%1,%2,%3};"
        : "+f"(c[0]), "+f"(c[1]), "+f"(c[2]), "+f"(c[3])
        : "r"(a[0]), "r"(a[1]), "r"(a[2]), "r"(a[3]),
          "r"(b[0]), "r"(b[1]));
}

__device__ __forceinline__ void cp16(unsigned* smem_dst, const float* gsrc) {
    unsigned u = (unsigned)__cvta_generic_to_shared(smem_dst);
    asm volatile("cp.async.cg.shared.global [%0], [%1], 16;" :: "r"(u), "l"(gsrc));
}

__device__ __forceinline__ void ldsm_x4(unsigned &d0, unsigned &d1,
                                        unsigned &d2, unsigned &d3, unsigned addr) {
    asm volatile("ldmatrix.sync.aligned.m8n8.x4.shared.b16 {%0,%1,%2,%3}, [%4];"
                 : "=r"(d0), "=r"(d1), "=r"(d2), "=r"(d3) : "r"(addr));
}

// ---------------- param prep ----------------
__global__ void prep_kernel(const float* __restrict__ rp_g, const float* __restrict__ rp_b,
                            const float* __restrict__ rp_m, const float* __restrict__ rp_v,
                            const float* __restrict__ rp_w1, const float* __restrict__ rp_w2,
                            const float* __restrict__ b1g, const float* __restrict__ b1b,
                            const float* __restrict__ b1m, const float* __restrict__ b1v,
                            const float* __restrict__ b2g, const float* __restrict__ b2b,
                            const float* __restrict__ b2m, const float* __restrict__ b2v)
{
    int t = threadIdx.x;
    int blk = blockIdx.x;
    if (blk < HH) {
        float acc = 0.f;
        #pragma unroll 8
        for (int o = 0; o < DD; o++)
            acc += rp_w2[(blk*DD + o)*CC + t];
        g_w2h[blk*CC + t] = acc;
    } else {
        float s = rp_g[t] * rsqrtf(rp_v[t] + EPSBN);
        g_u1x[t] = s * rp_w1[t*3 + 0];
        g_u1y[t] = s * rp_w1[t*3 + 1];
        g_u1z[t] = s * rp_w1[t*3 + 2];
        g_rpsh[t] = rp_b[t] - rp_m[t] * s;
        float s1 = b1g[t] * rsqrtf(b1v[t] + EPSBN);
        g_bn1s[t]  = s1;
        g_bn1sh[t] = b1b[t] - b1m[t] * s1;
        float s2 = b2g[t] * rsqrtf(b2v[t] + EPSBN);
        g_bn2s[t]  = s2;
        g_bn2sh[t] = b2b[t] - b2m[t] * s2;
    }
}

// ---------------- KNN: 2 queries per warp, exact-threshold buffered top-16 ----------------
// Each candidate float4 load is shared by 2 queries -> smem traffic halved vs
// 1 query/warp. Per-query state (top-16 in lanes 0-15, buffer, threshold) is
// the same verified structure as before.
__global__ __launch_bounds__(256)
void knn_kernel(const float* __restrict__ xyz)
{
    __shared__ float4 tp[1024];
    __shared__ float  sbK[8][2][64];
    __shared__ int    sbI[8][2][64];

    const int w = threadIdx.x >> 5, lane = threadIdx.x & 31;
    const int g0 = blockIdx.x * 16 + w * 2;     // query pair (same b: 16 | 4096)
    const int b  = g0 >> 12;
    const int n0 = g0 & (NN - 1), n1 = n0 + 1;
    const float* X = xyz + (size_t)b * 3 * NN;
    const float q0x = X[n0], q0y = X[NN + n0], q0z = X[2*NN + n0];
    const float q1x = X[n1], q1y = X[NN + n1], q1z = X[2*NN + n1];

    float curK0 = 1e30f, curK1 = 1e30f;
    int   curI0 = 0,     curI1 = 0;
    float W0 = 1e30f,    W1 = 1e30f;
    int   cnt0 = 0,      cnt1 = 0;

    auto rebuild = [&](float& curK, int& curI, float& W, int& cnt,
                       float* bK, int* bI) {
        __syncwarp();
        float c0 = (lane < 16) ? curK : 1e30f; int i0 = curI;
        float c1 = (lane      < cnt) ? bK[lane]      : 1e30f; int i1 = bI[lane];
        float c2 = (lane + 32 < cnt) ? bK[lane + 32] : 1e30f; int i2 = bI[lane + 32];
        float nk = 1e30f; int ni = 0;
        #pragma unroll
        for (int r = 0; r < KK; r++) {
            float m = c0; int mi = i0; int meta = (lane << 2);
            if (c1 < m) { m = c1; mi = i1; meta = (lane << 2) | 1; }
            if (c2 < m) { m = c2; mi = i2; meta = (lane << 2) | 2; }
            #pragma unroll
            for (int off = 16; off > 0; off >>= 1) {
                float om  = __shfl_xor_sync(0xffffffffu, m, off);
                int   omi = __shfl_xor_sync(0xffffffffu, mi, off);
                int   omt = __shfl_xor_sync(0xffffffffu, meta, off);
                if (om < m || (om == m && omt < meta)) { m = om; mi = omi; meta = omt; }
            }
            int wo = meta >> 2, ws = meta & 3;
            if (lane == wo) {
                if (ws == 0) c0 = 1e30f; else if (ws == 1) c1 = 1e30f; else c2 = 1e30f;
            }
            if (lane == r) { nk = m; ni = mi; }
            if (r == KK-1) W = m;
        }
        curK = nk; curI = ni;
        cnt = 0;
        __syncwarp();
    };

    for (int t = 0; t < 4; t++) {
        __syncthreads();
        for (int i = threadIdx.x; i < 1024; i += 256) {
            float px = X[t*1024 + i];
            float py = X[NN  + t*1024 + i];
            float pz = X[2*NN + t*1024 + i];
            tp[i] = make_float4(px, py, pz, fmaf(px, px, fmaf(py, py, pz*pz)));
        }
        __syncthreads();

        for (int jj = 0; jj < 32; jj++) {
            int ml = lane + 32*jj;
            float4 p = tp[ml];
            int idx = t*1024 + ml;
            float key0 = p.w - 2.f * fmaf(q0x, p.x, fmaf(q0y, p.y, q0z*p.z));
            float key1 = p.w - 2.f * fmaf(q1x, p.x, fmaf(q1y, p.y, q1z*p.z));
            unsigned bal0 = __ballot_sync(0xffffffffu, key0 < W0);
            if (bal0) {
                int pos = cnt0 + __popc(bal0 & ((1u << lane) - 1u));
                if (key0 < W0) { sbK[w][0][pos] = key0; sbI[w][0][pos] = idx; }
                cnt0 += __popc(bal0);
                if (cnt0 > 32) rebuild(curK0, curI0, W0, cnt0, sbK[w][0], sbI[w][0]);
            }
            unsigned bal1 = __ballot_sync(0xffffffffu, key1 < W1);
            if (bal1) {
                int pos = cnt1 + __popc(bal1 & ((1u << lane) - 1u));
                if (key1 < W1) { sbK[w][1][pos] = key1; sbI[w][1][pos] = idx; }
                cnt1 += __popc(bal1);
                if (cnt1 > 32) rebuild(curK1, curI1, W1, cnt1, sbK[w][1], sbI[w][1]);
            }
        }
    }
    rebuild(curK0, curI0, W0, cnt0, sbK[w][0], sbI[w][0]);
    rebuild(curK1, curI1, W1, cnt1, sbK[w][1], sbI[w][1]);

    if (lane < KK) {
        g_nbr[(size_t)g0 * KK + lane]       = curI0;
        g_nbr[(size_t)(g0 + 1) * KK + lane] = curI1;
    }
}

// ---------------- rel-pos bias kernel (register params; verified version) ----------------
__global__ __launch_bounds__(256, 2)
void bias_kernel(const float* __restrict__ xyz)
{
    int w = threadIdx.x >> 5, lane = threadIdx.x & 31;
    int g = blockIdx.x * 8 + w;
    int b = g >> 12, n = g & (NN - 1);

    float u1x[8], u1y[8], u1z[8], sh[8], w2r[HH][8];
    #pragma unroll
    for (int j = 0; j < 8; j++) {
        int c = lane + 32*j;
        u1x[j] = g_u1x[c]; u1y[j] = g_u1y[c]; u1z[j] = g_u1z[c];
        sh[j]  = g_rpsh[c];
        #pragma unroll
        for (int h = 0; h < HH; h++) w2r[h][j] = g_w2h[h*CC + c];
    }
    const float* Xp = xyz + (size_t)b * 3 * NN;
    float cx = Xp[n], cy = Xp[NN + n], cz = Xp[2*NN + n];

    const bool hi = lane >= 16;
    const bool b8 = (lane & 8) != 0;

    for (int k = 0; k < KK; k++) {
        int m = g_nbr[(size_t)g * KK + k];
        float rx = Xp[m] - cx, ry = Xp[NN + m] - cy, rz = Xp[2*NN + m] - cz;
        float bia[HH] = {0.f, 0.f, 0.f, 0.f};
        #pragma unroll
        for (int j = 0; j < 8; j++) {
            float h1 = fmaxf(fmaf(u1x[j], rx, fmaf(u1y[j], ry, fmaf(u1z[j], rz, sh[j]))), 0.f);
            #pragma unroll
            for (int h = 0; h < HH; h++)
                bia[h] = fmaf(w2r[h][j], h1, bia[h]);
        }
        float s0 = hi ? bia[2] : bia[0];
        float o0 = hi ? bia[0] : bia[2];
        float s1 = hi ? bia[3] : bia[1];
        float o1 = hi ? bia[1] : bia[3];
        s0 += __shfl_xor_sync(0xffffffffu, o0, 16);
        s1 += __shfl_xor_sync(0xffffffffu, o1, 16);
        float sA = b8 ? s1 : s0;
        float oA = b8 ? s0 : s1;
        sA += __shfl_xor_sync(0xffffffffu, oA, 8);
        sA += __shfl_xor_sync(0xffffffffu, sA, 4);
        sA += __shfl_xor_sync(0xffffffffu, sA, 2);
        sA += __shfl_xor_sync(0xffffffffu, sA, 1);
        if ((lane & 7) == 0)
            g_bias[((size_t)g * HH + (lane >> 3)) * KK + k] = sA;
    }
}

// ---------------- tf32 GEMM: 3-stage cp.async, XOR-swizzled A + ldmatrix ----------------
#define LDAW 32
#define LDB 136
#define A_WORDS (128*LDAW)
#define STAGE_WORDS (A_WORDS + 32*LDB)
#define GEMM_SMEM_BYTES (3*STAGE_WORDS*4)

template<int MODE>
__global__ __launch_bounds__(256, 2)
void gemm_tc(const float* __restrict__ W, const float* __restrict__ X,
             float* __restrict__ Y, int O, int C, int Nn,
             const float* __restrict__ bias,
             const float* __restrict__ resid,
             const float* __restrict__ bns, const float* __restrict__ bnsh,
             const float* __restrict__ W2, float* __restrict__ Y2)
{
    extern __shared__ unsigned sm[];

    const int b = blockIdx.z;
    X += (size_t)b * C * Nn;

    const float* Wp;
    float* Yp;
    int Ostr = 0, oB;
    if (MODE == 4) {
        int by = blockIdx.y;
        if (by < 2) { Wp = W;  Yp = Y  + (size_t)b * NN * CC;    Ostr = CC;    oB = by * 128; }
        else        { Wp = W2; Yp = Y2 + (size_t)b * NN * 2*CC;  Ostr = 2*CC;  oB = (by - 2) * 128; }
    } else {
        Wp = W; oB = blockIdx.y * 128;
        Yp = Y + (size_t)b * O * Nn;
        if (MODE == 2 || MODE == 3) resid += (size_t)b * O * Nn;
    }

    const int tid   = threadIdx.x;
    const int lane  = tid & 31;
    const int wid   = tid >> 5;
    const int warpM = wid >> 2;
    const int warpN = wid & 3;
    const int lr    = lane >> 2;
    const int lc    = lane & 3;
    const int n0    = blockIdx.x * 128;

    const int arow = tid >> 3;
    const int axw  = ((tid & 7) ^ (arow & 7)) * 4;
    const int akq  = (tid & 7) * 4;
    const int brow = tid >> 5, bnq = (tid & 31) * 4;

    const unsigned smbase = (unsigned)__cvta_generic_to_shared(sm);
    const int rw  = warpM * 64 + (lane & 15);
    const int x7  = lane & 7;
    const int hi16 = (lane >> 4) & 1;

    float acc[4][4][4];
    #pragma unroll
    for (int mt = 0; mt < 4; mt++)
        #pragma unroll
        for (int nt = 0; nt < 4; nt++)
            #pragma unroll
            for (int r = 0; r < 4; r++) acc[mt][nt][r] = 0.f;

    const int ntiles = C >> 5;

    #pragma unroll
    for (int p = 0; p < 2; p++) {
        unsigned* As = sm + p*STAGE_WORDS; unsigned* Bs = As + A_WORDS;
        int kt = p << 5;
        #pragma unroll
        for (int i = 0; i < 4; i++)
            cp16(&As[(arow + 32*i) * LDAW + axw],
                 &Wp[(size_t)(oB + arow + 32*i) * C + kt + akq]);
        #pragma unroll
        for (int i = 0; i < 4; i++)
            cp16(&Bs[(brow + 8*i) * LDB + bnq], &X[(size_t)(kt + brow + 8*i) * Nn + n0 + bnq]);
        asm volatile("cp.async.commit_group;");
    }

    int sNext = 2;
    for (int it = 0; it < ntiles; it++) {
        asm volatile("cp.async.wait_group %0;" :: "n"(1));
        __syncthreads();

        if (it + 2 < ntiles) {
            int ktn = (it + 2) << 5;
            unsigned* As = sm + sNext*STAGE_WORDS; unsigned* Bs = As + A_WORDS;
            #pragma unroll
            for (int i = 0; i < 4; i++)
                cp16(&As[(arow + 32*i) * LDAW + axw],
                     &Wp[(size_t)(oB + arow + 32*i) * C + ktn + akq]);
            #pragma unroll
            for (int i = 0; i < 4; i++)
                cp16(&Bs[(brow + 8*i) * LDB + bnq], &X[(size_t)(ktn + brow + 8*i) * Nn + n0 + bnq]);
        }
        asm volatile("cp.async.commit_group;");

        int sCur = sNext + 1; if (sCur >= 3) sCur -= 3;
        const unsigned aStage = smbase + (unsigned)(sCur*STAGE_WORDS)*4u;
        const unsigned* Bs = sm + sCur*STAGE_WORDS + A_WORDS;
        #pragma unroll
        for (int kk = 0; kk < 4; kk++) {
            const int kb = kk * 8;
            const int ch = 2*kk + hi16;
            unsigned afr[4][4], bfr[4][2];
            #pragma unroll
            for (int mt = 0; mt < 4; mt++) {
                unsigned addr = aStage +
                    ((unsigned)(((rw + mt*16) * LDAW) + ((ch ^ x7) << 2)) << 2);
                ldsm_x4(afr[mt][0], afr[mt][1], afr[mt][2], afr[mt][3], addr);
            }
            #pragma unroll
            for (int nt = 0; nt < 4; nt++) {
                int cb = warpN * 32 + nt * 8 + lr;
                bfr[nt][0] = Bs[(kb + lc)     * LDB + cb];
                bfr[nt][1] = Bs[(kb + 4 + lc) * LDB + cb];
            }
            #pragma unroll
            for (int mt = 0; mt < 4; mt++)
                #pragma unroll
                for (int nt = 0; nt < 4; nt++)
                    mma_tf32(acc[mt][nt], afr[mt], bfr[nt]);
        }
        sNext = sCur;
    }

    if (MODE == 4) {
        __syncthreads();
        float* stg = reinterpret_cast<float*>(sm);   // [128][132]
        #pragma unroll
        for (int mt = 0; mt < 4; mt++) {
            int ol = warpM * 64 + mt * 16 + lr;
            #pragma unroll
            for (int nt = 0; nt < 4; nt++) {
                int nl = warpN * 32 + nt * 8 + lc * 2;
                stg[nl      * 132 + ol]     = acc[mt][nt][0];
                stg[(nl + 1)* 132 + ol]     = acc[mt][nt][1];
                stg[nl      * 132 + ol + 8] = acc[mt][nt][2];
                stg[(nl + 1)* 132 + ol + 8] = acc[mt][nt][3];
            }
        }
        __syncthreads();
        #pragma unroll
        for (int r = wid; r < 128; r += 8) {
            float4 v = *reinterpret_cast<float4*>(&stg[r * 132 + lane * 4]);
            *reinterpret_cast<float4*>(&Yp[(size_t)(n0 + r) * Ostr + oB + lane * 4]) = v;
        }
        return;
    }

    #pragma unroll
    for (int mt = 0; mt < 4; mt++) {
        int o = oB + warpM * 64 + mt * 16 + lr;
        #pragma unroll
        for (int nt = 0; nt < 4; nt++) {
            int n = n0 + warpN * 32 + nt * 8 + lc * 2;
            float2 p0 = make_float2(acc[mt][nt][0], acc[mt][nt][1]);
            float2 p1 = make_float2(acc[mt][nt][2], acc[mt][nt][3]);
            size_t i0 = (size_t)o * Nn + n;
            size_t i1 = (size_t)(o + 8) * Nn + n;
            if (MODE == 1) {
                float b0 = bias[o], b1 = bias[o + 8];
                p0.x = fmaxf(p0.x + b0, 0.f); p0.y = fmaxf(p0.y + b0, 0.f);
                p1.x = fmaxf(p1.x + b1, 0.f); p1.y = fmaxf(p1.y + b1, 0.f);
            } else if (MODE == 2) {
                float s0 = bns[o], h0 = bnsh[o];
                float s1 = bns[o + 8], h1 = bnsh[o + 8];
                float2 r0 = *reinterpret_cast<const float2*>(&resid[i0]);
                float2 r1 = *reinterpret_cast<const float2*>(&resid[i1]);
                p0.x = (p0.x + r0.x) * s0 + h0; p0.y = (p0.y + r0.y) * s0 + h0;
                p1.x = (p1.x + r1.x) * s1 + h1; p1.y = (p1.y + r1.y) * s1 + h1;
            } else if (MODE == 3) {
                float s0 = bns[o], h0 = bnsh[o], bo0 = bias[o];
                float s1 = bns[o + 8], h1 = bnsh[o + 8], bo1 = bias[o + 8];
                float2 r0 = *reinterpret_cast<const float2*>(&resid[i0]);
                float2 r1 = *reinterpret_cast<const float2*>(&resid[i1]);
                p0.x = (p0.x + bo0 + r0.x) * s0 + h0; p0.y = (p0.y + bo0 + r0.y) * s0 + h0;
                p1.x = (p1.x + bo1 + r1.x) * s1 + h1; p1.y = (p1.y + bo1 + r1.y) * s1 + h1;
            }
            *reinterpret_cast<float2*>(&Yp[i0]) = p0;
            *reinterpret_cast<float2*>(&Yp[i1]) = p1;
        }
    }
}

// ---------------- attention (slim) ----------------
__global__ __launch_bounds__(256, 4)
void attn_kernel()
{
    __shared__ int   sIdx[8][KK];
    __shared__ float sLog[8][HH][KK];
    __shared__ float sOut[CC][9];

    int w = threadIdx.x >> 5, lane = threadIdx.x & 31;
    int g = blockIdx.x * 8 + w;
    int b = g >> 12;

    if (lane < KK) sIdx[w][lane] = g_nbr[(size_t)g * KK + lane];
    __syncwarp();

    float qreg[8];
    #pragma unroll
    for (int j = 0; j < 8; j++)
        qreg[j] = g_qT[(size_t)g * CC + lane + 32*j];

    const bool hi = lane >= 16;
    const bool b8 = (lane & 8) != 0;

    for (int k = 0; k < KK; k++) {
        int m = sIdx[w][k];
        const float* kvp = &g_kvT[((size_t)b * NN + m) * (2*CC)];
        float qk[HH] = {0.f, 0.f, 0.f, 0.f};
        #pragma unroll
        for (int j = 0; j < 8; j++)
            qk[j >> 1] = fmaf(qreg[j], kvp[lane + 32*j], qk[j >> 1]);

        float s0 = hi ? qk[2] : qk[0];
        float o0 = hi ? qk[0] : qk[2];
        float s1 = hi ? qk[3] : qk[1];
        float o1 = hi ? qk[1] : qk[3];
        s0 += __shfl_xor_sync(0xffffffffu, o0, 16);
        s1 += __shfl_xor_sync(0xffffffffu, o1, 16);
        float sA = b8 ? s1 : s0;
        float oA = b8 ? s0 : s1;
        sA += __shfl_xor_sync(0xffffffffu, oA, 8);
        sA += __shfl_xor_sync(0xffffffffu, sA, 4);
        sA += __shfl_xor_sync(0xffffffffu, sA, 2);
        sA += __shfl_xor_sync(0xffffffffu, sA, 1);
        if ((lane & 7) == 0) sLog[w][lane >> 3][k] = sA * SCALE;
    }
    __syncwarp();

    if (lane < HH) {
        const float* bp = &g_bias[((size_t)g * HH + lane) * KK];
        float lg[KK];
        float mx = -1e30f;
        #pragma unroll
        for (int k = 0; k < KK; k++) {
            lg[k] = sLog[w][lane][k] + bp[k];
            mx = fmaxf(mx, lg[k]);
        }
        float s = 0.f;
        #pragma unroll
        for (int k = 0; k < KK; k++) {
            float e = __expf(lg[k] - mx);
            lg[k] = e;
            s += e;
        }
        float inv = 1.f / s;
        #pragma unroll
        for (int k = 0; k < KK; k++) sLog[w][lane][k] = lg[k] * inv;
    }
    __syncwarp();

    float acc[8] = {0,0,0,0,0,0,0,0};
    for (int k = 0; k < KK; k++) {
        int m = sIdx[w][k];
        const float* vp = &g_kvT[((size_t)b * NN + m) * (2*CC) + CC];
        #pragma unroll
        for (int j = 0; j < 8; j++)
            acc[j] = fmaf(sLog[w][j >> 1][k], vp[lane + 32*j], acc[j]);
    }
    #pragma unroll
    for (int j = 0; j < 8; j++) sOut[lane + 32*j][w] = acc[j];
    __syncthreads();

    int t = threadIdx.x;
    int bb = (blockIdx.x * 8) >> 12;
    int n0 = (blockIdx.x * 8) & (NN - 1);
    float4 v0 = make_float4(sOut[t][0], sOut[t][1], sOut[t][2], sOut[t][3]);
    float4 v1 = make_float4(sOut[t][4], sOut[t][5], sOut[t][6], sOut[t][7]);
    float* op = &g_ao[((size_t)bb * CC + t) * NN + n0];
    *reinterpret_cast<float4*>(op)     = v0;
    *reinterpret_cast<float4*>(op + 4) = v1;
}

// ---------------- launch ----------------
extern "C" void kernel_launch(void* const* d_in, const int* in_sizes, int n_in,
                              void* d_out, int out_size)
{
    const float* x      = (const float*)d_in[0];
    const float* xyz    = (const float*)d_in[1];
    const float* Wq     = (const float*)d_in[2];
    const float* Wkv    = (const float*)d_in[3];
    const float* Wproj  = (const float*)d_in[4];
    const float* rp_w1  = (const float*)d_in[5];
    const float* rp_g   = (const float*)d_in[6];
    const float* rp_b   = (const float*)d_in[7];
    const float* rp_m   = (const float*)d_in[8];
    const float* rp_v   = (const float*)d_in[9];
    const float* rp_w2  = (const float*)d_in[10];
    const float* bn1_g  = (const float*)d_in[11];
    const float* bn1_b  = (const float*)d_in[12];
    const float* bn1_m  = (const float*)d_in[13];
    const float* bn1_v  = (const float*)d_in[14];
    const float* bn2_g  = (const float*)d_in[15];
    const float* bn2_b  = (const float*)d_in[16];
    const float* bn2_m  = (const float*)d_in[17];
    const float* bn2_v  = (const float*)d_in[18];
    const float* ffn_w1 = (const float*)d_in[19];
    const float* ffn_b1 = (const float*)d_in[20];
    const float* ffn_w2 = (const float*)d_in[21];
    const float* ffn_b2 = (const float*)d_in[22];
    float* out = (float*)d_out;

    float *p_qT, *p_kvT, *p_ao, *p_x1, *p_h;
    float *p_bn1s, *p_bn1sh, *p_bn2s, *p_bn2sh;
    cudaGetSymbolAddress((void**)&p_qT,   g_qT);
    cudaGetSymbolAddress((void**)&p_kvT,  g_kvT);
    cudaGetSymbolAddress((void**)&p_ao,   g_ao);
    cudaGetSymbolAddress((void**)&p_x1,   g_x1);
    cudaGetSymbolAddress((void**)&p_h,    g_hbuf);
    cudaGetSymbolAddress((void**)&p_bn1s, g_bn1s);
    cudaGetSymbolAddress((void**)&p_bn1sh,g_bn1sh);
    cudaGetSymbolAddress((void**)&p_bn2s, g_bn2s);
    cudaGetSymbolAddress((void**)&p_bn2sh,g_bn2sh);

    cudaFuncSetAttribute(gemm_tc<1>, cudaFuncAttributeMaxDynamicSharedMemorySize, GEMM_SMEM_BYTES);
    cudaFuncSetAttribute(gemm_tc<2>, cudaFuncAttributeMaxDynamicSharedMemorySize, GEMM_SMEM_BYTES);
    cudaFuncSetAttribute(gemm_tc<3>, cudaFuncAttributeMaxDynamicSharedMemorySize, GEMM_SMEM_BYTES);
    cudaFuncSetAttribute(gemm_tc<4>, cudaFuncAttributeMaxDynamicSharedMemorySize, GEMM_SMEM_BYTES);

    cudaStream_t s2;
    cudaEvent_t eF, eP, eJ;
    cudaStreamCreateWithFlags(&s2, cudaStreamNonBlocking);
    cudaEventCreateWithFlags(&eF, cudaEventDisableTiming);
    cudaEventCreateWithFlags(&eP, cudaEventDisableTiming);
    cudaEventCreateWithFlags(&eJ, cudaEventDisableTiming);

    cudaEventRecord(eF, 0);
    cudaStreamWaitEvent(s2, eF, 0);
    knn_kernel<<<BB*NN/16, 256, 0, s2>>>(xyz);

    prep_kernel<<<5, 256>>>(rp_g, rp_b, rp_m, rp_v, rp_w1, rp_w2,
                            bn1_g, bn1_b, bn1_m, bn1_v,
                            bn2_g, bn2_b, bn2_m, bn2_v);
    cudaEventRecord(eP, 0);

    cudaStreamWaitEvent(s2, eP, 0);
    bias_kernel<<<BB*NN/8, 256, 0, s2>>>(xyz);
    cudaEventRecord(eJ, s2);

    gemm_tc<4><<<dim3(NN/128, 6, BB), 256, GEMM_SMEM_BYTES>>>(
        Wq, x, p_qT, CC, CC, NN, nullptr, nullptr, nullptr, nullptr, Wkv, p_kvT);

    cudaStreamWaitEvent(0, eJ, 0);

    attn_kernel<<<BB*NN/8, 256>>>();

    gemm_tc<2><<<dim3(NN/128, CC/128, BB), 256, GEMM_SMEM_BYTES>>>(
        Wproj, p_ao, p_x1, CC, CC, NN, nullptr, x, p_bn1s, p_bn1sh, nullptr, nullptr);
    gemm_tc<1><<<dim3(NN/128, 4*CC/128, BB), 256, GEMM_SMEM_BYTES>>>(
        ffn_w1, p_x1, p_h, 4*CC, CC, NN, ffn_b1, nullptr, nullptr, nullptr, nullptr, nullptr);
    gemm_tc<3><<<dim3(NN/128, CC/128, BB), 256, GEMM_SMEM_BYTES>>>(
        ffn_w2, p_h, out, CC, 4*CC, NN, ffn_b2, p_x1, p_bn2s, p_bn2sh, nullptr, nullptr);

    (void)in_sizes; (void)n_in; (void)out_size;
}

// round 17
// speedup vs baseline: 1.0674x; 1.0674x over previous
#include <cuda_runtime.h>
#include <math.h>

#define BB 2
#define CC 256
#define NN 4096
#define HH 4
#define KK 16
#define DD 64
#define EPSBN 1e-5f
#define SCALE 0.125f

// ---------------- scratch ----------------
__device__ float g_qT  [BB*NN*CC];
__device__ float g_kvT [BB*NN*2*CC];
__device__ float g_ao  [BB*CC*NN];
__device__ float g_x1  [BB*CC*NN];
__device__ float g_hbuf[BB*4*CC*NN];
__device__ int   g_nbr [BB*NN*KK];
__device__ float g_bias[BB*NN*HH*KK];
__device__ float g_w2h [HH*CC];
__device__ float g_u1x [CC], g_u1y[CC], g_u1z[CC];
__device__ float g_rpsh[CC];
__device__ float g_bn1s[CC], g_bn1sh[CC];
__device__ float g_bn2s[CC], g_bn2sh[CC];

// ---------------- helpers ----------------
__device__ __forceinline__ void mma_tf32(float c[4],
                                         const unsigned a[4],
                                         const unsigned b[2]) {
    asm volatile(
        "mma.sync.aligned.m16n8k8.row.col.f32.tf32.tf32.f32 "
        "{%0,%1,%2,%3}, {%4,%5,%6,%7}, {%8,%9}, {%0,%1,%2,%3};"
        : "+f"(c[0]), "+f"(c[1]), "+f"(c[2]), "+f"(c[3])
        : "r"(a[0]), "r"(a[1]), "r"(a[2]), "r"(a[3]),
          "r"(b[0]), "r"(b[1]));
}

__device__ __forceinline__ void cp16(unsigned* smem_dst, const float* gsrc) {
    unsigned u = (unsigned)__cvta_generic_to_shared(smem_dst);
    asm volatile("cp.async.cg.shared.global [%0], [%1], 16;" :: "r"(u), "l"(gsrc));
}

__device__ __forceinline__ void ldsm_x4(unsigned &d0, unsigned &d1,
                                        unsigned &d2, unsigned &d3, unsigned addr) {
    asm volatile("ldmatrix.sync.aligned.m8n8.x4.shared.b16 {%0,%1,%2,%3}, [%4];"
                 : "=r"(d0), "=r"(d1), "=r"(d2), "=r"(d3) : "r"(addr));
}

// ---------------- param prep ----------------
__global__ void prep_kernel(const float* __restrict__ rp_g, const float* __restrict__ rp_b,
                            const float* __restrict__ rp_m, const float* __restrict__ rp_v,
                            const float* __restrict__ rp_w1, const float* __restrict__ rp_w2,
                            const float* __restrict__ b1g, const float* __restrict__ b1b,
                            const float* __restrict__ b1m, const float* __restrict__ b1v,
                            const float* __restrict__ b2g, const float* __restrict__ b2b,
                            const float* __restrict__ b2m, const float* __restrict__ b2v)
{
    int t = threadIdx.x;
    int blk = blockIdx.x;
    if (blk < HH) {
        float acc = 0.f;
        #pragma unroll 8
        for (int o = 0; o < DD; o++)
            acc += rp_w2[(blk*DD + o)*CC + t];
        g_w2h[blk*CC + t] = acc;
    } else {
        float s = rp_g[t] * rsqrtf(rp_v[t] + EPSBN);
        g_u1x[t] = s * rp_w1[t*3 + 0];
        g_u1y[t] = s * rp_w1[t*3 + 1];
        g_u1z[t] = s * rp_w1[t*3 + 2];
        g_rpsh[t] = rp_b[t] - rp_m[t] * s;
        float s1 = b1g[t] * rsqrtf(b1v[t] + EPSBN);
        g_bn1s[t]  = s1;
        g_bn1sh[t] = b1b[t] - b1m[t] * s1;
        float s2 = b2g[t] * rsqrtf(b2v[t] + EPSBN);
        g_bn2s[t]  = s2;
        g_bn2sh[t] = b2b[t] - b2m[t] * s2;
    }
}

// ---------------- KNN: warp-wide exact-threshold buffered top-16 ----------------
__global__ __launch_bounds__(256)
void knn_kernel(const float* __restrict__ xyz)
{
    __shared__ float4 tp[1024];
    __shared__ float  sbK[8][64];
    __shared__ int    sbI[8][64];

    const int w = threadIdx.x >> 5, lane = threadIdx.x & 31;
    const int g = blockIdx.x * 8 + w;
    const int b = g >> 12, n = g & (NN - 1);
    const float* X = xyz + (size_t)b * 3 * NN;
    const float qx = X[n], qy = X[NN + n], qz = X[2*NN + n];

    float curK = 1e30f; int curI = 0;
    float W = 1e30f;
    int cnt = 0;

    auto rebuild = [&]() {
        __syncwarp();
        float c0 = (lane < 16) ? curK : 1e30f; int i0 = curI;
        float c1 = (lane      < cnt) ? sbK[w][lane]      : 1e30f; int i1 = sbI[w][lane];
        float c2 = (lane + 32 < cnt) ? sbK[w][lane + 32] : 1e30f; int i2 = sbI[w][lane + 32];
        float nk = 1e30f; int ni = 0;
        #pragma unroll
        for (int r = 0; r < KK; r++) {
            float m = c0; int mi = i0; int meta = (lane << 2);
            if (c1 < m) { m = c1; mi = i1; meta = (lane << 2) | 1; }
            if (c2 < m) { m = c2; mi = i2; meta = (lane << 2) | 2; }
            #pragma unroll
            for (int off = 16; off > 0; off >>= 1) {
                float om  = __shfl_xor_sync(0xffffffffu, m, off);
                int   omi = __shfl_xor_sync(0xffffffffu, mi, off);
                int   omt = __shfl_xor_sync(0xffffffffu, meta, off);
                if (om < m || (om == m && omt < meta)) { m = om; mi = omi; meta = omt; }
            }
            int wo = meta >> 2, ws = meta & 3;
            if (lane == wo) {
                if (ws == 0) c0 = 1e30f; else if (ws == 1) c1 = 1e30f; else c2 = 1e30f;
            }
            if (lane == r) { nk = m; ni = mi; }
            if (r == KK-1) W = m;
        }
        curK = nk; curI = ni;
        cnt = 0;
        __syncwarp();
    };

    for (int t = 0; t < 4; t++) {
        __syncthreads();
        for (int i = threadIdx.x; i < 1024; i += 256) {
            float px = X[t*1024 + i];
            float py = X[NN  + t*1024 + i];
            float pz = X[2*NN + t*1024 + i];
            tp[i] = make_float4(px, py, pz, fmaf(px, px, fmaf(py, py, pz*pz)));
        }
        __syncthreads();

        for (int jj = 0; jj < 32; jj++) {
            int ml = lane + 32*jj;
            float4 p = tp[ml];
            float key = p.w - 2.f * fmaf(qx, p.x, fmaf(qy, p.y, qz*p.z));
            bool pass = key < W;
            unsigned bal = __ballot_sync(0xffffffffu, pass);
            if (bal) {
                int pos = cnt + __popc(bal & ((1u << lane) - 1u));
                if (pass) { sbK[w][pos] = key; sbI[w][pos] = t*1024 + ml; }
                cnt += __popc(bal);
                if (cnt > 32) rebuild();
            }
        }
    }
    rebuild();

    if (lane < KK) g_nbr[(size_t)g * KK + lane] = curI;
}

// ---------------- rel-pos bias kernel ----------------
__global__ __launch_bounds__(256, 2)
void bias_kernel(const float* __restrict__ xyz)
{
    int w = threadIdx.x >> 5, lane = threadIdx.x & 31;
    int g = blockIdx.x * 8 + w;
    int b = g >> 12, n = g & (NN - 1);

    float u1x[8], u1y[8], u1z[8], sh[8], w2r[HH][8];
    #pragma unroll
    for (int j = 0; j < 8; j++) {
        int c = lane + 32*j;
        u1x[j] = g_u1x[c]; u1y[j] = g_u1y[c]; u1z[j] = g_u1z[c];
        sh[j]  = g_rpsh[c];
        #pragma unroll
        for (int h = 0; h < HH; h++) w2r[h][j] = g_w2h[h*CC + c];
    }
    const float* Xp = xyz + (size_t)b * 3 * NN;
    float cx = Xp[n], cy = Xp[NN + n], cz = Xp[2*NN + n];

    const bool hi = lane >= 16;
    const bool b8 = (lane & 8) != 0;

    for (int k = 0; k < KK; k++) {
        int m = g_nbr[(size_t)g * KK + k];
        float rx = Xp[m] - cx, ry = Xp[NN + m] - cy, rz = Xp[2*NN + m] - cz;
        float bia[HH] = {0.f, 0.f, 0.f, 0.f};
        #pragma unroll
        for (int j = 0; j < 8; j++) {
            float h1 = fmaxf(fmaf(u1x[j], rx, fmaf(u1y[j], ry, fmaf(u1z[j], rz, sh[j]))), 0.f);
            #pragma unroll
            for (int h = 0; h < HH; h++)
                bia[h] = fmaf(w2r[h][j], h1, bia[h]);
        }
        float s0 = hi ? bia[2] : bia[0];
        float o0 = hi ? bia[0] : bia[2];
        float s1 = hi ? bia[3] : bia[1];
        float o1 = hi ? bia[1] : bia[3];
        s0 += __shfl_xor_sync(0xffffffffu, o0, 16);
        s1 += __shfl_xor_sync(0xffffffffu, o1, 16);
        float sA = b8 ? s1 : s0;
        float oA = b8 ? s0 : s1;
        sA += __shfl_xor_sync(0xffffffffu, oA, 8);
        sA += __shfl_xor_sync(0xffffffffu, sA, 4);
        sA += __shfl_xor_sync(0xffffffffu, sA, 2);
        sA += __shfl_xor_sync(0xffffffffu, sA, 1);
        if ((lane & 7) == 0)
            g_bias[((size_t)g * HH + (lane >> 3)) * KK + k] = sA;
    }
}

// ---------------- tf32 GEMM: 3-stage cp.async, XOR-swizzled A + ldmatrix ----------------
#define LDAW 32
#define LDB 136
#define A_WORDS (128*LDAW)
#define STAGE_WORDS (A_WORDS + 32*LDB)
#define GEMM_SMEM_BYTES (3*STAGE_WORDS*4)

template<int MODE>
__global__ __launch_bounds__(256, 2)
void gemm_tc(const float* __restrict__ W, const float* __restrict__ X,
             float* __restrict__ Y, int O, int C, int Nn,
             const float* __restrict__ bias,
             const float* __restrict__ resid,
             const float* __restrict__ bns, const float* __restrict__ bnsh,
             const float* __restrict__ W2, float* __restrict__ Y2)
{
    extern __shared__ unsigned sm[];

    const int b = blockIdx.z;
    X += (size_t)b * C * Nn;

    const float* Wp;
    float* Yp;
    int Ostr = 0, oB;
    if (MODE == 4) {
        int by = blockIdx.y;
        if (by < 2) { Wp = W;  Yp = Y  + (size_t)b * NN * CC;    Ostr = CC;    oB = by * 128; }
        else        { Wp = W2; Yp = Y2 + (size_t)b * NN * 2*CC;  Ostr = 2*CC;  oB = (by - 2) * 128; }
    } else {
        Wp = W; oB = blockIdx.y * 128;
        Yp = Y + (size_t)b * O * Nn;
        if (MODE == 2 || MODE == 3) resid += (size_t)b * O * Nn;
    }

    const int tid   = threadIdx.x;
    const int lane  = tid & 31;
    const int wid   = tid >> 5;
    const int warpM = wid >> 2;
    const int warpN = wid & 3;
    const int lr    = lane >> 2;
    const int lc    = lane & 3;
    const int n0    = blockIdx.x * 128;

    const int arow = tid >> 3;
    const int axw  = ((tid & 7) ^ (arow & 7)) * 4;
    const int akq  = (tid & 7) * 4;
    const int brow = tid >> 5, bnq = (tid & 31) * 4;

    const unsigned smbase = (unsigned)__cvta_generic_to_shared(sm);
    const int rw  = warpM * 64 + (lane & 15);
    const int x7  = lane & 7;
    const int hi16 = (lane >> 4) & 1;

    float acc[4][4][4];
    #pragma unroll
    for (int mt = 0; mt < 4; mt++)
        #pragma unroll
        for (int nt = 0; nt < 4; nt++)
            #pragma unroll
            for (int r = 0; r < 4; r++) acc[mt][nt][r] = 0.f;

    const int ntiles = C >> 5;

    #pragma unroll
    for (int p = 0; p < 2; p++) {
        unsigned* As = sm + p*STAGE_WORDS; unsigned* Bs = As + A_WORDS;
        int kt = p << 5;
        #pragma unroll
        for (int i = 0; i < 4; i++)
            cp16(&As[(arow + 32*i) * LDAW + axw],
                 &Wp[(size_t)(oB + arow + 32*i) * C + kt + akq]);
        #pragma unroll
        for (int i = 0; i < 4; i++)
            cp16(&Bs[(brow + 8*i) * LDB + bnq], &X[(size_t)(kt + brow + 8*i) * Nn + n0 + bnq]);
        asm volatile("cp.async.commit_group;");
    }

    int sNext = 2;
    for (int it = 0; it < ntiles; it++) {
        asm volatile("cp.async.wait_group %0;" :: "n"(1));
        __syncthreads();

        if (it + 2 < ntiles) {
            int ktn = (it + 2) << 5;
            unsigned* As = sm + sNext*STAGE_WORDS; unsigned* Bs = As + A_WORDS;
            #pragma unroll
            for (int i = 0; i < 4; i++)
                cp16(&As[(arow + 32*i) * LDAW + axw],
                     &Wp[(size_t)(oB + arow + 32*i) * C + ktn + akq]);
            #pragma unroll
            for (int i = 0; i < 4; i++)
                cp16(&Bs[(brow + 8*i) * LDB + bnq], &X[(size_t)(ktn + brow + 8*i) * Nn + n0 + bnq]);
        }
        asm volatile("cp.async.commit_group;");

        int sCur = sNext + 1; if (sCur >= 3) sCur -= 3;
        const unsigned aStage = smbase + (unsigned)(sCur*STAGE_WORDS)*4u;
        const unsigned* Bs = sm + sCur*STAGE_WORDS + A_WORDS;
        #pragma unroll
        for (int kk = 0; kk < 4; kk++) {
            const int kb = kk * 8;
            const int ch = 2*kk + hi16;
            unsigned afr[4][4], bfr[4][2];
            #pragma unroll
            for (int mt = 0; mt < 4; mt++) {
                unsigned addr = aStage +
                    ((unsigned)(((rw + mt*16) * LDAW) + ((ch ^ x7) << 2)) << 2);
                ldsm_x4(afr[mt][0], afr[mt][1], afr[mt][2], afr[mt][3], addr);
            }
            #pragma unroll
            for (int nt = 0; nt < 4; nt++) {
                int cb = warpN * 32 + nt * 8 + lr;
                bfr[nt][0] = Bs[(kb + lc)     * LDB + cb];
                bfr[nt][1] = Bs[(kb + 4 + lc) * LDB + cb];
            }
            #pragma unroll
            for (int mt = 0; mt < 4; mt++)
                #pragma unroll
                for (int nt = 0; nt < 4; nt++)
                    mma_tf32(acc[mt][nt], afr[mt], bfr[nt]);
        }
        sNext = sCur;
    }

    if (MODE == 4) {
        __syncthreads();
        float* stg = reinterpret_cast<float*>(sm);   // [128][132]
        #pragma unroll
        for (int mt = 0; mt < 4; mt++) {
            int ol = warpM * 64 + mt * 16 + lr;
            #pragma unroll
            for (int nt = 0; nt < 4; nt++) {
                int nl = warpN * 32 + nt * 8 + lc * 2;
                stg[nl      * 132 + ol]     = acc[mt][nt][0];
                stg[(nl + 1)* 132 + ol]     = acc[mt][nt][1];
                stg[nl      * 132 + ol + 8] = acc[mt][nt][2];
                stg[(nl + 1)* 132 + ol + 8] = acc[mt][nt][3];
            }
        }
        __syncthreads();
        #pragma unroll
        for (int r = wid; r < 128; r += 8) {
            float4 v = *reinterpret_cast<float4*>(&stg[r * 132 + lane * 4]);
            *reinterpret_cast<float4*>(&Yp[(size_t)(n0 + r) * Ostr + oB + lane * 4]) = v;
        }
        return;
    }

    #pragma unroll
    for (int mt = 0; mt < 4; mt++) {
        int o = oB + warpM * 64 + mt * 16 + lr;
        #pragma unroll
        for (int nt = 0; nt < 4; nt++) {
            int n = n0 + warpN * 32 + nt * 8 + lc * 2;
            float2 p0 = make_float2(acc[mt][nt][0], acc[mt][nt][1]);
            float2 p1 = make_float2(acc[mt][nt][2], acc[mt][nt][3]);
            size_t i0 = (size_t)o * Nn + n;
            size_t i1 = (size_t)(o + 8) * Nn + n;
            if (MODE == 1) {
                float b0 = bias[o], b1 = bias[o + 8];
                p0.x = fmaxf(p0.x + b0, 0.f); p0.y = fmaxf(p0.y + b0, 0.f);
                p1.x = fmaxf(p1.x + b1, 0.f); p1.y = fmaxf(p1.y + b1, 0.f);
            } else if (MODE == 2) {
                float s0 = bns[o], h0 = bnsh[o];
                float s1 = bns[o + 8], h1 = bnsh[o + 8];
                float2 r0 = *reinterpret_cast<const float2*>(&resid[i0]);
                float2 r1 = *reinterpret_cast<const float2*>(&resid[i1]);
                p0.x = (p0.x + r0.x) * s0 + h0; p0.y = (p0.y + r0.y) * s0 + h0;
                p1.x = (p1.x + r1.x) * s1 + h1; p1.y = (p1.y + r1.y) * s1 + h1;
            } else if (MODE == 3) {
                float s0 = bns[o], h0 = bnsh[o], bo0 = bias[o];
                float s1 = bns[o + 8], h1 = bnsh[o + 8], bo1 = bias[o + 8];
                float2 r0 = *reinterpret_cast<const float2*>(&resid[i0]);
                float2 r1 = *reinterpret_cast<const float2*>(&resid[i1]);
                p0.x = (p0.x + bo0 + r0.x) * s0 + h0; p0.y = (p0.y + bo0 + r0.y) * s0 + h0;
                p1.x = (p1.x + bo1 + r1.x) * s1 + h1; p1.y = (p1.y + bo1 + r1.y) * s1 + h1;
            }
            *reinterpret_cast<float2*>(&Yp[i0]) = p0;
            *reinterpret_cast<float2*>(&Yp[i1]) = p1;
        }
    }
}

// ---------------- attention (slim) ----------------
__global__ __launch_bounds__(256, 4)
void attn_kernel()
{
    __shared__ int   sIdx[8][KK];
    __shared__ float sLog[8][HH][KK];
    __shared__ float sOut[CC][9];

    int w = threadIdx.x >> 5, lane = threadIdx.x & 31;
    int g = blockIdx.x * 8 + w;
    int b = g >> 12;

    if (lane < KK) sIdx[w][lane] = g_nbr[(size_t)g * KK + lane];
    __syncwarp();

    float qreg[8];
    #pragma unroll
    for (int j = 0; j < 8; j++)
        qreg[j] = g_qT[(size_t)g * CC + lane + 32*j];

    const bool hi = lane >= 16;
    const bool b8 = (lane & 8) != 0;

    for (int k = 0; k < KK; k++) {
        int m = sIdx[w][k];
        const float* kvp = &g_kvT[((size_t)b * NN + m) * (2*CC)];
        float qk[HH] = {0.f, 0.f, 0.f, 0.f};
        #pragma unroll
        for (int j = 0; j < 8; j++)
            qk[j >> 1] = fmaf(qreg[j], kvp[lane + 32*j], qk[j >> 1]);

        float s0 = hi ? qk[2] : qk[0];
        float o0 = hi ? qk[0] : qk[2];
        float s1 = hi ? qk[3] : qk[1];
        float o1 = hi ? qk[1] : qk[3];
        s0 += __shfl_xor_sync(0xffffffffu, o0, 16);
        s1 += __shfl_xor_sync(0xffffffffu, o1, 16);
        float sA = b8 ? s1 : s0;
        float oA = b8 ? s0 : s1;
        sA += __shfl_xor_sync(0xffffffffu, oA, 8);
        sA += __shfl_xor_sync(0xffffffffu, sA, 4);
        sA += __shfl_xor_sync(0xffffffffu, sA, 2);
        sA += __shfl_xor_sync(0xffffffffu, sA, 1);
        if ((lane & 7) == 0) sLog[w][lane >> 3][k] = sA * SCALE;
    }
    __syncwarp();

    if (lane < HH) {
        const float* bp = &g_bias[((size_t)g * HH + lane) * KK];
        float lg[KK];
        float mx = -1e30f;
        #pragma unroll
        for (int k = 0; k < KK; k++) {
            lg[k] = sLog[w][lane][k] + bp[k];
            mx = fmaxf(mx, lg[k]);
        }
        float s = 0.f;
        #pragma unroll
        for (int k = 0; k < KK; k++) {
            float e = __expf(lg[k] - mx);
            lg[k] = e;
            s += e;
        }
        float inv = 1.f / s;
        #pragma unroll
        for (int k = 0; k < KK; k++) sLog[w][lane][k] = lg[k] * inv;
    }
    __syncwarp();

    float acc[8] = {0,0,0,0,0,0,0,0};
    for (int k = 0; k < KK; k++) {
        int m = sIdx[w][k];
        const float* vp = &g_kvT[((size_t)b * NN + m) * (2*CC) + CC];
        #pragma unroll
        for (int j = 0; j < 8; j++)
            acc[j] = fmaf(sLog[w][j >> 1][k], vp[lane + 32*j], acc[j]);
    }
    #pragma unroll
    for (int j = 0; j < 8; j++) sOut[lane + 32*j][w] = acc[j];
    __syncthreads();

    int t = threadIdx.x;
    int bb = (blockIdx.x * 8) >> 12;
    int n0 = (blockIdx.x * 8) & (NN - 1);
    float4 v0 = make_float4(sOut[t][0], sOut[t][1], sOut[t][2], sOut[t][3]);
    float4 v1 = make_float4(sOut[t][4], sOut[t][5], sOut[t][6], sOut[t][7]);
    float* op = &g_ao[((size_t)bb * CC + t) * NN + n0];
    *reinterpret_cast<float4*>(op)     = v0;
    *reinterpret_cast<float4*>(op + 4) = v1;
}

// ---------------- launch ----------------
extern "C" void kernel_launch(void* const* d_in, const int* in_sizes, int n_in,
                              void* d_out, int out_size)
{
    const float* x      = (const float*)d_in[0];
    const float* xyz    = (const float*)d_in[1];
    const float* Wq     = (const float*)d_in[2];
    const float* Wkv    = (const float*)d_in[3];
    const float* Wproj  = (const float*)d_in[4];
    const float* rp_w1  = (const float*)d_in[5];
    const float* rp_g   = (const float*)d_in[6];
    const float* rp_b   = (const float*)d_in[7];
    const float* rp_m   = (const float*)d_in[8];
    const float* rp_v   = (const float*)d_in[9];
    const float* rp_w2  = (const float*)d_in[10];
    const float* bn1_g  = (const float*)d_in[11];
    const float* bn1_b  = (const float*)d_in[12];
    const float* bn1_m  = (const float*)d_in[13];
    const float* bn1_v  = (const float*)d_in[14];
    const float* bn2_g  = (const float*)d_in[15];
    const float* bn2_b  = (const float*)d_in[16];
    const float* bn2_m  = (const float*)d_in[17];
    const float* bn2_v  = (const float*)d_in[18];
    const float* ffn_w1 = (const float*)d_in[19];
    const float* ffn_b1 = (const float*)d_in[20];
    const float* ffn_w2 = (const float*)d_in[21];
    const float* ffn_b2 = (const float*)d_in[22];
    float* out = (float*)d_out;

    float *p_qT, *p_kvT, *p_ao, *p_x1, *p_h;
    float *p_bn1s, *p_bn1sh, *p_bn2s, *p_bn2sh;
    cudaGetSymbolAddress((void**)&p_qT,   g_qT);
    cudaGetSymbolAddress((void**)&p_kvT,  g_kvT);
    cudaGetSymbolAddress((void**)&p_ao,   g_ao);
    cudaGetSymbolAddress((void**)&p_x1,   g_x1);
    cudaGetSymbolAddress((void**)&p_h,    g_hbuf);
    cudaGetSymbolAddress((void**)&p_bn1s, g_bn1s);
    cudaGetSymbolAddress((void**)&p_bn1sh,g_bn1sh);
    cudaGetSymbolAddress((void**)&p_bn2s, g_bn2s);
    cudaGetSymbolAddress((void**)&p_bn2sh,g_bn2sh);

    cudaFuncSetAttribute(gemm_tc<1>, cudaFuncAttributeMaxDynamicSharedMemorySize, GEMM_SMEM_BYTES);
    cudaFuncSetAttribute(gemm_tc<2>, cudaFuncAttributeMaxDynamicSharedMemorySize, GEMM_SMEM_BYTES);
    cudaFuncSetAttribute(gemm_tc<3>, cudaFuncAttributeMaxDynamicSharedMemorySize, GEMM_SMEM_BYTES);
    cudaFuncSetAttribute(gemm_tc<4>, cudaFuncAttributeMaxDynamicSharedMemorySize, GEMM_SMEM_BYTES);

    cudaStream_t s2;
    cudaEvent_t eF, eP, eJ;
    cudaStreamCreateWithFlags(&s2, cudaStreamNonBlocking);
    cudaEventCreateWithFlags(&eF, cudaEventDisableTiming);
    cudaEventCreateWithFlags(&eP, cudaEventDisableTiming);
    cudaEventCreateWithFlags(&eJ, cudaEventDisableTiming);

    cudaEventRecord(eF, 0);
    cudaStreamWaitEvent(s2, eF, 0);
    knn_kernel<<<BB*NN/8, 256, 0, s2>>>(xyz);

    prep_kernel<<<5, 256>>>(rp_g, rp_b, rp_m, rp_v, rp_w1, rp_w2,
                            bn1_g, bn1_b, bn1_m, bn1_v,
                            bn2_g, bn2_b, bn2_m, bn2_v);
    cudaEventRecord(eP, 0);

    cudaStreamWaitEvent(s2, eP, 0);
    bias_kernel<<<BB*NN/8, 256, 0, s2>>>(xyz);
    cudaEventRecord(eJ, s2);

    gemm_tc<4><<<dim3(NN/128, 6, BB), 256, GEMM_SMEM_BYTES>>>(
        Wq, x, p_qT, CC, CC, NN, nullptr, nullptr, nullptr, nullptr, Wkv, p_kvT);

    cudaStreamWaitEvent(0, eJ, 0);

    attn_kernel<<<BB*NN/8, 256>>>();

    gemm_tc<2><<<dim3(NN/128, CC/128, BB), 256, GEMM_SMEM_BYTES>>>(
        Wproj, p_ao, p_x1, CC, CC, NN, nullptr, x, p_bn1s, p_bn1sh, nullptr, nullptr);
    gemm_tc<1><<<dim3(NN/128, 4*CC/128, BB), 256, GEMM_SMEM_BYTES>>>(
        ffn_w1, p_x1, p_h, 4*CC, CC, NN, ffn_b1, nullptr, nullptr, nullptr, nullptr, nullptr);
    gemm_tc<3><<<dim3(NN/128, CC/128, BB), 256, GEMM_SMEM_BYTES>>>(
        ffn_w2, p_h, out, CC, 4*CC, NN, ffn_b2, p_x1, p_bn2s, p_bn2sh, nullptr, nullptr);

    (void)in_sizes; (void)n_in; (void)out_size;
}